// round 7
// baseline (speedup 1.0000x reference)
#include <cuda_runtime.h>

// NAM_42442866819214 — ONE fused kernel.
// (R6 hung: __ballot_sync was inside an `if (lane==0)` — warp-collective in
// divergent branch = deadlock. Fixed: collective executed by all lanes.)
//
// Math collapse (per-feature, valid when b1[f,:]==0 && b2[f,:]==0, verified
// at runtime into g_mode[f]):
//   relu(x*w) = x * (x>0 ? max(w,0) : min(w,0))
//   contrib(b,f) = x * (x>0 ? dpos[f] : dneg[f]) + b3[f]
//
// Structure (512 blocks x 256 thr, all wave-1 resident at 4 blocks/SM):
//   every block : prefetch its 16 input rows + b3 + bias into registers
//   blocks 0-127: fold W1,W2,W3 -> dpos/dneg for ONE feature (8 warps split
//                 the H1 loop), publish, atomicAdd(g_ready)
//   every block : 1-thread nanosleep-spin until g_ready==128 (hidden under
//                 the input prefetch already in flight)
//   every block : 2-scalar piecewise-linear map, store contribs, row sums
//   last block  : reset g_ready/g_done (graph-replay deterministic)

#define NB   8192
#define NF   128
#define NH1  64
#define NH2  32
#define GRID 512
#define RPB  16    // rows per block = 8 warps * 2 rows

__device__ float g_dpos[NF];
__device__ float g_dneg[NF];
__device__ int   g_mode[NF];
__device__ int   g_ready;   // zero-init; reset at end of every launch
__device__ int   g_done;    // zero-init; reset at end of every launch

// Dead unless b1/b2 nonzero; kept for correctness on arbitrary bias values.
__device__ __noinline__ float mlp_full(float x, int f,
                                       const float* __restrict__ W1,
                                       const float* __restrict__ b1,
                                       const float* __restrict__ W2,
                                       const float* __restrict__ b2,
                                       const float* __restrict__ W3) {
    float acc = 0.f;
    for (int k = 0; k < NH2; k++) {
        float a = b2[f * NH2 + k];
        for (int i = 0; i < NH1; i++) {
            float h1 = fmaxf(fmaf(x, W1[f * NH1 + i], b1[f * NH1 + i]), 0.f);
            a = fmaf(h1, W2[(f * NH1 + i) * NH2 + k], a);
        }
        acc = fmaf(fmaxf(a, 0.f), W3[f * NH2 + k], acc);
    }
    return acc;
}

__global__ void __launch_bounds__(256, 4)
nam_fused(const float* __restrict__ inputs,
          const float* __restrict__ W1,
          const float* __restrict__ b1,
          const float* __restrict__ W2,
          const float* __restrict__ b2,
          const float* __restrict__ W3,
          const float* __restrict__ b3,
          const float* __restrict__ bias,
          float* __restrict__ out) {
    const int tid  = threadIdx.x;
    const int lane = tid & 31;
    const int warp = tid >> 5;           // 0..7
    const int b0   = blockIdx.x * RPB + warp;
    const int f0   = lane * 4;

    const float4* in4 = (const float4*)inputs;
    float4*       c4  = (float4*)(out + NB);

    // ---- prefetch inputs (independent of precompute) — issue FIRST -------
    float4 x0 = in4[b0 * (NF / 4) + lane];
    float4 x1 = in4[(b0 + 8) * (NF / 4) + lane];
    const float4 b34   = ((const float4*)b3)[lane];
    const float  bias0 = bias[0];

    // ---- precompute (blocks 0..127, one feature each) --------------------
    __shared__ float s_cp[8][32], s_cn[8][32];
    __shared__ int   s_nz[8];
    if (blockIdx.x < NF) {
        const int f = blockIdx.x;
        const int k = lane;

        int nz = 0;
        if (tid < NH1)            nz = (b1[f * NH1 + tid] != 0.f);
        else if (tid < NH1 + NH2) nz = (b2[f * NH2 + tid - NH1] != 0.f);
        // warp-collective executed by ALL lanes (R6 bug was here)
        int wnz = __ballot_sync(0xffffffffu, nz) ? 1 : 0;

        float cp = 0.f, cn = 0.f;
#pragma unroll
        for (int j = 0; j < 8; j++) {
            const int i = warp * 8 + j;
            float w  = W1[f * NH1 + i];               // warp-uniform
            float w2 = W2[(f * NH1 + i) * NH2 + k];   // coalesced
            cp = fmaf(w2, fmaxf(w, 0.f), cp);
            cn = fmaf(w2, fminf(w, 0.f), cn);
        }
        s_cp[warp][k] = cp;
        s_cn[warp][k] = cn;
        if (lane == 0) s_nz[warp] = wnz;
        __syncthreads();

        if (warp == 0) {
            float tcp = 0.f, tcn = 0.f;
#pragma unroll
            for (int wsum = 0; wsum < 8; wsum++) {
                tcp += s_cp[wsum][k];
                tcn += s_cn[wsum][k];
            }
            float w3 = W3[f * NH2 + k];
            float dp = w3 * fmaxf(tcp, 0.f);
            float dn = w3 * fminf(tcn, 0.f);
#pragma unroll
            for (int o = 16; o > 0; o >>= 1) {
                dp += __shfl_xor_sync(0xffffffffu, dp, o);
                dn += __shfl_xor_sync(0xffffffffu, dn, o);
            }
            if (k == 0) {
                int m = s_nz[0] | s_nz[1] | s_nz[2] | s_nz[3] |
                        s_nz[4] | s_nz[5] | s_nz[6] | s_nz[7];
                g_dpos[f] = dp;
                g_dneg[f] = dn;
                g_mode[f] = m;
                __threadfence();
                atomicAdd(&g_ready, 1);
            }
        }
    }

    // ---- wait for all 128 features to be published ------------------------
    if (tid == 0) {
        while (*(volatile int*)&g_ready < NF) { __nanosleep(32); }
    }
    __syncthreads();

    // ---- stream ------------------------------------------------------------
    const float4 dp4 = __ldcg(&((const float4*)g_dpos)[lane]);
    const float4 dn4 = __ldcg(&((const float4*)g_dneg)[lane]);
    const int4   m4  = __ldcg(&((const int4*)g_mode)[lane]);
    const bool fast = (m4.x | m4.y | m4.z | m4.w) == 0;

#pragma unroll
    for (int r = 0; r < 2; r++) {
        const int b = b0 + r * 8;
        const float4 x = r ? x1 : x0;
        float4 c;
        if (fast) {
            c.x = fmaf(x.x, (x.x > 0.f ? dp4.x : dn4.x), b34.x);
            c.y = fmaf(x.y, (x.y > 0.f ? dp4.y : dn4.y), b34.y);
            c.z = fmaf(x.z, (x.z > 0.f ? dp4.z : dn4.z), b34.z);
            c.w = fmaf(x.w, (x.w > 0.f ? dp4.w : dn4.w), b34.w);
        } else {
            c.x = mlp_full(x.x, f0 + 0, W1, b1, W2, b2, W3) + b34.x;
            c.y = mlp_full(x.y, f0 + 1, W1, b1, W2, b2, W3) + b34.y;
            c.z = mlp_full(x.z, f0 + 2, W1, b1, W2, b2, W3) + b34.z;
            c.w = mlp_full(x.w, f0 + 3, W1, b1, W2, b2, W3) + b34.w;
        }
        c4[b * (NF / 4) + lane] = c;

        float s = (c.x + c.y) + (c.z + c.w);
#pragma unroll
        for (int o = 16; o > 0; o >>= 1)
            s += __shfl_xor_sync(0xffffffffu, s, o);
        if (lane == 0) out[b] = s + bias0;
    }

    // ---- reset counters so every graph replay starts clean -----------------
    __syncthreads();
    if (tid == 0) {
        if (atomicAdd(&g_done, 1) == GRID - 1) {
            g_ready = 0;
            g_done  = 0;
            __threadfence();
        }
    }
}

extern "C" void kernel_launch(void* const* d_in, const int* in_sizes, int n_in,
                              void* d_out, int out_size) {
    const float* inputs = (const float*)d_in[0];
    const float* W1     = (const float*)d_in[1];
    const float* b1     = (const float*)d_in[2];
    const float* W2     = (const float*)d_in[3];
    const float* b2     = (const float*)d_in[4];
    const float* W3     = (const float*)d_in[5];
    const float* b3     = (const float*)d_in[6];
    const float* bias   = (const float*)d_in[7];

    nam_fused<<<GRID, 256>>>(inputs, W1, b1, W2, b2, W3, b3, bias,
                             (float*)d_out);
}

// round 8
// speedup vs baseline: 1.6846x; 1.6846x over previous
#include <cuda_runtime.h>

// NAM_42442866819214 — 2 kernels + PDL (measured best structure: R3=8.67us;
// single fused kernel with in-kernel sync measured 15us — abandoned).
//
// Collapse (per-feature, valid when b1[f,:]==0 && b2[f,:]==0, verified at
// runtime into g_mode[f]):
//   relu(x*w) = x * (x>0 ? max(w,0) : min(w,0))
//   contrib(b,f) = x * (x>0 ? dpos[f] : dneg[f]) + b3[f]
//
// nam_pre : 128 blocks x 256 thr — 8 warps split the H1 fold (8 W2 loads per
//           thread), 2-stage smem reduce. PDL-triggers at entry.
// nam_main: 512 blocks x 128 thr — all wave-1 resident; warp w owns rows
//           {bid*16 + r*4 + w}. Inputs/b3/bias prefetched BEFORE
//           cudaGridDependencySynchronize(); post-sync work = FMA + stores.

#define NB   8192
#define NF   128
#define NH1  64
#define NH2  32
#define GRID 512
#define RPB  16    // rows per block = 4 warps * 4 rows

__device__ float g_dpos[NF];
__device__ float g_dneg[NF];
__device__ int   g_mode[NF];   // 0 = fast path valid (rewritten every launch)

// ---------------------------------------------------------------- precompute
__global__ void __launch_bounds__(256)
nam_pre(const float* __restrict__ W1,
        const float* __restrict__ b1,
        const float* __restrict__ W2,
        const float* __restrict__ b2,
        const float* __restrict__ W3) {
    cudaTriggerProgrammaticLaunchCompletion();

    const int f    = blockIdx.x;
    const int tid  = threadIdx.x;
    const int lane = tid & 31;   // H2 unit k
    const int warp = tid >> 5;   // i-chunk 0..7
    const int k    = lane;

    int nz = 0;
    if (tid < NH1)            nz = (b1[f * NH1 + tid] != 0.f);
    else if (tid < NH1 + NH2) nz = (b2[f * NH2 + tid - NH1] != 0.f);
    int wnz = __ballot_sync(0xffffffffu, nz) ? 1 : 0;   // all lanes execute

    float cp = 0.f, cn = 0.f;
#pragma unroll
    for (int j = 0; j < 8; j++) {
        const int i = warp * 8 + j;
        float w  = W1[f * NH1 + i];               // warp-uniform
        float w2 = W2[(f * NH1 + i) * NH2 + k];   // coalesced
        cp = fmaf(w2, fmaxf(w, 0.f), cp);
        cn = fmaf(w2, fminf(w, 0.f), cn);
    }

    __shared__ float s_cp[8][32], s_cn[8][32];
    __shared__ int   s_nz[8];
    s_cp[warp][k] = cp;
    s_cn[warp][k] = cn;
    if (lane == 0) s_nz[warp] = wnz;
    __syncthreads();

    if (warp == 0) {
        float tcp = 0.f, tcn = 0.f;
#pragma unroll
        for (int w8 = 0; w8 < 8; w8++) {
            tcp += s_cp[w8][k];
            tcn += s_cn[w8][k];
        }
        float w3 = W3[f * NH2 + k];
        float dp = w3 * fmaxf(tcp, 0.f);   // x>0: relu(x*cp) = x*max(cp,0)
        float dn = w3 * fminf(tcn, 0.f);   // x<0: relu(x*cn) = x*min(cn,0)
#pragma unroll
        for (int o = 16; o > 0; o >>= 1) {
            dp += __shfl_xor_sync(0xffffffffu, dp, o);
            dn += __shfl_xor_sync(0xffffffffu, dn, o);
        }
        if (k == 0) {
            g_dpos[f] = dp;
            g_dneg[f] = dn;
            g_mode[f] = s_nz[0] | s_nz[1] | s_nz[2] | s_nz[3] |
                        s_nz[4] | s_nz[5] | s_nz[6] | s_nz[7];
        }
    }
}

// ------------------------------------------------------------------ fallback
// Dead unless b1/b2 nonzero; __noinline__ + tight launch bounds push its
// state to spills, keeping the fast path's register budget small.
__device__ __noinline__ float mlp_full(float x, int f,
                                       const float* __restrict__ W1,
                                       const float* __restrict__ b1,
                                       const float* __restrict__ W2,
                                       const float* __restrict__ b2,
                                       const float* __restrict__ W3) {
    float acc = 0.f;
    for (int k = 0; k < NH2; k++) {
        float a = b2[f * NH2 + k];
        for (int i = 0; i < NH1; i++) {
            float h1 = fmaxf(fmaf(x, W1[f * NH1 + i], b1[f * NH1 + i]), 0.f);
            a = fmaf(h1, W2[(f * NH1 + i) * NH2 + k], a);
        }
        acc = fmaf(fmaxf(a, 0.f), W3[f * NH2 + k], acc);
    }
    return acc;
}

// ---------------------------------------------------------------------- main
// grid 512 x 128. Warp w (0..3) of block B owns rows {B*16 + r*4 + w, r=0..3}.
__global__ void __launch_bounds__(128, 8)
nam_main(const float* __restrict__ inputs,
         const float* __restrict__ W1,
         const float* __restrict__ b1,
         const float* __restrict__ W2,
         const float* __restrict__ b2,
         const float* __restrict__ W3,
         const float* __restrict__ b3,
         const float* __restrict__ bias,
         float* __restrict__ out) {
    const int lane = threadIdx.x & 31;
    const int warp = threadIdx.x >> 5;   // 0..3
    const int b0   = blockIdx.x * RPB + warp;
    const int f0   = lane * 4;

    const float4* in4 = (const float4*)inputs;
    float4*       c4  = (float4*)(out + NB);

    // ---- prefetch everything independent of nam_pre ----------------------
    float4 x[4];
#pragma unroll
    for (int r = 0; r < 4; r++)
        x[r] = in4[(b0 + r * 4) * (NF / 4) + lane];
    const float4 b34   = ((const float4*)b3)[lane];
    const float  bias0 = bias[0];

    // ---- wait for nam_pre --------------------------------------------------
    cudaGridDependencySynchronize();

    const float4 dp4 = ((const float4*)g_dpos)[lane];
    const float4 dn4 = ((const float4*)g_dneg)[lane];
    const int4   m4  = ((const int4*)g_mode)[lane];
    const bool fast = (m4.x | m4.y | m4.z | m4.w) == 0;

#pragma unroll
    for (int r = 0; r < 4; r++) {
        const int b = b0 + r * 4;
        float4 c;
        if (fast) {
            c.x = fmaf(x[r].x, (x[r].x > 0.f ? dp4.x : dn4.x), b34.x);
            c.y = fmaf(x[r].y, (x[r].y > 0.f ? dp4.y : dn4.y), b34.y);
            c.z = fmaf(x[r].z, (x[r].z > 0.f ? dp4.z : dn4.z), b34.z);
            c.w = fmaf(x[r].w, (x[r].w > 0.f ? dp4.w : dn4.w), b34.w);
        } else {
            c.x = mlp_full(x[r].x, f0 + 0, W1, b1, W2, b2, W3) + b34.x;
            c.y = mlp_full(x[r].y, f0 + 1, W1, b1, W2, b2, W3) + b34.y;
            c.z = mlp_full(x[r].z, f0 + 2, W1, b1, W2, b2, W3) + b34.z;
            c.w = mlp_full(x[r].w, f0 + 3, W1, b1, W2, b2, W3) + b34.w;
        }
        c4[b * (NF / 4) + lane] = c;

        float s = (c.x + c.y) + (c.z + c.w);
#pragma unroll
        for (int o = 16; o > 0; o >>= 1)
            s += __shfl_xor_sync(0xffffffffu, s, o);
        if (lane == 0) out[b] = s + bias0;
    }
}

// -------------------------------------------------------------------- launch
extern "C" void kernel_launch(void* const* d_in, const int* in_sizes, int n_in,
                              void* d_out, int out_size) {
    const float* inputs = (const float*)d_in[0];
    const float* W1     = (const float*)d_in[1];
    const float* b1     = (const float*)d_in[2];
    const float* W2     = (const float*)d_in[3];
    const float* b2     = (const float*)d_in[4];
    const float* W3     = (const float*)d_in[5];
    const float* b3     = (const float*)d_in[6];
    const float* bias   = (const float*)d_in[7];
    float* out = (float*)d_out;

    nam_pre<<<NF, 256>>>(W1, b1, W2, b2, W3);

    cudaLaunchConfig_t cfg = {};
    cfg.gridDim  = dim3(GRID, 1, 1);
    cfg.blockDim = dim3(128, 1, 1);
    cfg.dynamicSmemBytes = 0;
    cfg.stream = 0;
    cudaLaunchAttribute attr[1];
    attr[0].id = cudaLaunchAttributeProgrammaticStreamSerialization;
    attr[0].val.programmaticStreamSerializationAllowed = 1;
    cfg.attrs = attr;
    cfg.numAttrs = 1;
    cudaLaunchKernelEx(&cfg, nam_main,
                       inputs, W1, b1, W2, b2, W3, b3, bias, out);
}